// round 1
// baseline (speedup 1.0000x reference)
#include <cuda_runtime.h>
#include <cstdint>

#define N_V 8192
#define N_E 4096
#define FT  512
#define WN  256   // words per HTB row  (N_V/32)
#define WE  128   // words per HB  row  (N_E/32)

// ---------------- scratch (static device globals; no allocation) ------------
__device__ uint32_t g_HB [N_V * WE];    // row bits: bit k of word j of row n  = H[n][j*32+k]
__device__ uint32_t g_HTB[N_E * WN];    // col bits: bit k of word j of col e  = H[j*32+k][e]
__device__ float    g_edge_emb[N_E * FT];
__device__ float    g_hw  [N_E];
__device__ float    g_dege[N_E];
__device__ float    g_degv[N_V];
__device__ float    g_out0[(size_t)N_V * FT];
__device__ float    g_t   [N_E * FT];

// ---------------- bitmask builders ------------------------------------------
__global__ void k_build_HB(const float* __restrict__ H) {
    int idx = blockIdx.x * blockDim.x + threadIdx.x;   // n*WE + w
    int n = idx >> 7;
    int w = idx & 127;
    const float4* p = reinterpret_cast<const float4*>(H + (size_t)n * N_E + w * 32);
    uint32_t bits = 0;
#pragma unroll
    for (int i = 0; i < 8; i++) {
        float4 v = p[i];
        if (v.x != 0.f) bits |= 1u << (i * 4 + 0);
        if (v.y != 0.f) bits |= 1u << (i * 4 + 1);
        if (v.z != 0.f) bits |= 1u << (i * 4 + 2);
        if (v.w != 0.f) bits |= 1u << (i * 4 + 3);
    }
    g_HB[idx] = bits;
}

__global__ void k_build_HTB(const float* __restrict__ H) {
    __shared__ float tile[32][257];
    int e0 = blockIdx.x * 256;
    int n0 = blockIdx.y * 32;
    int t  = threadIdx.x;
#pragma unroll 4
    for (int i = 0; i < 32; i++)
        tile[i][t] = H[(size_t)(n0 + i) * N_E + e0 + t];
    __syncthreads();
    int w = t >> 5, l = t & 31;
#pragma unroll 4
    for (int j = 0; j < 32; j++) {
        int c = w * 32 + j;
        uint32_t m = __ballot_sync(0xffffffffu, tile[l][c] != 0.f);
        if (l == 0) g_HTB[(size_t)(e0 + c) * WN + blockIdx.y] = m;
    }
}

// ---------------- edge_emb = H^T @ x  (gather rows of x per edge) -----------
__global__ void __launch_bounds__(128) k_edge_gather_x(const float* __restrict__ x) {
    int e = blockIdx.x;
    int tid = threadIdx.x;                 // feature float4 index 0..127
    __shared__ uint32_t words[WN];
    for (int i = tid; i < WN; i += 128) words[i] = g_HTB[(size_t)e * WN + i];
    __syncthreads();
    float4 acc = {0.f, 0.f, 0.f, 0.f};
    const float4* x4 = reinterpret_cast<const float4*>(x);
    for (int j = 0; j < WN; j++) {
        uint32_t w = words[j];
        while (w) {
            int k = __ffs(w) - 1; w &= w - 1;
            int n = j * 32 + k;
            float4 v = x4[(size_t)n * 128 + tid];
            acc.x += v.x; acc.y += v.y; acc.z += v.z; acc.w += v.w;
        }
    }
    reinterpret_cast<float4*>(g_edge_emb)[(size_t)e * 128 + tid] = acc;
}

// ---------------- hw = sigmoid(edge_emb @ V), deg_e, write w output ---------
__global__ void __launch_bounds__(128) k_hw_dege(const float* __restrict__ V,
                                                 float* __restrict__ w_out) {
    int e = blockIdx.x * 4 + (threadIdx.x >> 5);
    int l = threadIdx.x & 31;
    float s = 0.f;
#pragma unroll
    for (int i = 0; i < 16; i++) {
        int f = i * 32 + l;
        s += g_edge_emb[(size_t)e * FT + f] * V[f];
    }
#pragma unroll
    for (int o = 16; o; o >>= 1) s += __shfl_xor_sync(0xffffffffu, s, o);
    float hw = 1.f / (1.f + expf(-s));
    int cnt = 0;
#pragma unroll
    for (int i = 0; i < 8; i++) cnt += __popc(g_HTB[(size_t)e * WN + l * 8 + i]);
#pragma unroll
    for (int o = 16; o; o >>= 1) cnt += __shfl_xor_sync(0xffffffffu, cnt, o);
    if (l == 0) {
        g_hw[e]   = hw;
        w_out[e]  = hw;
        g_dege[e] = (float)cnt;
    }
}

// ---------------- deg_v = H @ hw --------------------------------------------
__global__ void __launch_bounds__(128) k_degv() {
    int n = blockIdx.x * 4 + (threadIdx.x >> 5);
    int l = threadIdx.x & 31;
    float s = 0.f;
#pragma unroll
    for (int jj = 0; jj < 4; jj++) {
        int j = l * 4 + jj;
        uint32_t w = g_HB[(size_t)n * WE + j];
        while (w) { int k = __ffs(w) - 1; w &= w - 1; s += g_hw[j * 32 + k]; }
    }
#pragma unroll
    for (int o = 16; o; o >>= 1) s += __shfl_xor_sync(0xffffffffu, s, o);
    if (l == 0) g_degv[n] = s;
}

// ---------------- out0 = x @ weight  (fp32 SGEMM 128x128x16) ----------------
__global__ void __launch_bounds__(256) k_gemm_xw(const float* __restrict__ A,
                                                 const float* __restrict__ B) {
    __shared__ float As[16][132];
    __shared__ float Bs[16][132];
    int bm = blockIdx.y * 128;
    int bn = blockIdx.x * 128;
    int tid = threadIdx.x;
    int tx = tid & 15, ty = tid >> 4;
    float acc[8][8];
#pragma unroll
    for (int i = 0; i < 8; i++)
#pragma unroll
        for (int j = 0; j < 8; j++) acc[i][j] = 0.f;

    for (int k0 = 0; k0 < FT; k0 += 16) {
#pragma unroll
        for (int r = 0; r < 2; r++) {
            int id = tid + r * 256;
            int ar = id >> 2, ac = (id & 3) * 4;
            float4 av = *reinterpret_cast<const float4*>(&A[(size_t)(bm + ar) * FT + k0 + ac]);
            As[ac + 0][ar] = av.x; As[ac + 1][ar] = av.y;
            As[ac + 2][ar] = av.z; As[ac + 3][ar] = av.w;
            int br = id >> 5, bc = (id & 31) * 4;
            *reinterpret_cast<float4*>(&Bs[br][bc]) =
                *reinterpret_cast<const float4*>(&B[(size_t)(k0 + br) * FT + bn + bc]);
        }
        __syncthreads();
#pragma unroll
        for (int kk = 0; kk < 16; kk++) {
            float a[8], b[8];
#pragma unroll
            for (int i = 0; i < 8; i++) a[i] = As[kk][ty + 16 * i];
#pragma unroll
            for (int i = 0; i < 8; i++) b[i] = Bs[kk][tx + 16 * i];
#pragma unroll
            for (int i = 0; i < 8; i++)
#pragma unroll
                for (int j = 0; j < 8; j++)
                    acc[i][j] += a[i] * b[j];
        }
        __syncthreads();
    }
#pragma unroll
    for (int i = 0; i < 8; i++)
#pragma unroll
        for (int j = 0; j < 8; j++)
            g_out0[(size_t)(bm + ty + 16 * i) * FT + bn + tx + 16 * j] = acc[i][j];
}

// ------------ t = (w*deg_e) ⊙ H^T @ (deg_v ⊙ out0) --------------------------
__global__ void __launch_bounds__(128) k_edge_gather_t() {
    int e = blockIdx.x;
    int tid = threadIdx.x;
    __shared__ uint32_t words[WN];
    for (int i = tid; i < WN; i += 128) words[i] = g_HTB[(size_t)e * WN + i];
    __syncthreads();
    float4 acc = {0.f, 0.f, 0.f, 0.f};
    const float4* o4 = reinterpret_cast<const float4*>(g_out0);
    for (int j = 0; j < WN; j++) {
        uint32_t w = words[j];
        while (w) {
            int k = __ffs(w) - 1; w &= w - 1;
            int n = j * 32 + k;
            float dv = g_degv[n];
            float4 v = o4[(size_t)n * 128 + tid];
            acc.x += dv * v.x; acc.y += dv * v.y;
            acc.z += dv * v.z; acc.w += dv * v.w;
        }
    }
    float s = g_hw[e] * g_dege[e];
    float4 r = {s * acc.x, s * acc.y, s * acc.z, s * acc.w};
    reinterpret_cast<float4*>(g_t)[(size_t)e * 128 + tid] = r;
}

// ------------ out = deg_v ⊙ (H @ t) + bias ----------------------------------
__global__ void __launch_bounds__(128) k_vertex_gather(const float* __restrict__ bias,
                                                       float* __restrict__ out) {
    int n = blockIdx.x;
    int tid = threadIdx.x;
    __shared__ uint32_t words[WE];
    if (tid < WE) words[tid] = g_HB[(size_t)n * WE + tid];
    __syncthreads();
    float4 acc = {0.f, 0.f, 0.f, 0.f};
    const float4* t4 = reinterpret_cast<const float4*>(g_t);
    for (int j = 0; j < WE; j++) {
        uint32_t w = words[j];
        while (w) {
            int k = __ffs(w) - 1; w &= w - 1;
            int e = j * 32 + k;
            float4 v = t4[(size_t)e * 128 + tid];
            acc.x += v.x; acc.y += v.y; acc.z += v.z; acc.w += v.w;
        }
    }
    float dv = g_degv[n];
    float4 b = reinterpret_cast<const float4*>(bias)[tid];
    float4 r = {dv * acc.x + b.x, dv * acc.y + b.y,
                dv * acc.z + b.z, dv * acc.w + b.w};
    reinterpret_cast<float4*>(out)[(size_t)n * 128 + tid] = r;
}

// ---------------- launch ----------------------------------------------------
extern "C" void kernel_launch(void* const* d_in, const int* in_sizes, int n_in,
                              void* d_out, int out_size) {
    const float* x      = (const float*)d_in[0];   // (8192, 512)
    const float* H      = (const float*)d_in[1];   // (8192, 4096)
    const float* weight = (const float*)d_in[2];   // (512, 512)
    const float* V      = (const float*)d_in[3];   // (512, 1)
    const float* bias   = (const float*)d_in[4];   // (512,)
    float* out   = (float*)d_out;                  // (8192, 512)
    float* w_out = (float*)d_out + (size_t)N_V * FT;  // (4096,)

    k_build_HB <<<(N_V * WE) / 256, 256>>>(H);
    k_build_HTB<<<dim3(N_E / 256, N_V / 32), 256>>>(H);
    k_edge_gather_x<<<N_E, 128>>>(x);
    k_hw_dege<<<N_E / 4, 128>>>(V, w_out);
    k_degv<<<N_V / 4, 128>>>();
    k_gemm_xw<<<dim3(FT / 128, N_V / 128), 256>>>(x, weight);
    k_edge_gather_t<<<N_E, 128>>>();
    k_vertex_gather<<<N_V, 128>>>(bias, out);
}

// round 4
// speedup vs baseline: 2.5706x; 2.5706x over previous
#include <cuda_runtime.h>
#include <cstdint>

#define N_V 8192
#define N_E 4096
#define FT  512
#define WN  256   // words per HTB row  (N_V/32)
#define WE  128   // words per HB  row  (N_E/32)

// ---------------- scratch (static device globals; no allocation) ------------
__device__ uint32_t g_HB [N_V * WE];    // bit k of word j of row n  = H[n][j*32+k]
__device__ uint32_t g_HTB[N_E * WN];    // bit k of word j of col e  = H[j*32+k][e]
__device__ float    g_y   [N_V];        // y = x @ V
__device__ float    g_hw  [N_E];
__device__ float    g_dege[N_E];
__device__ float    g_degv[N_V];
__device__ float    g_z   [(size_t)N_V * FT];   // z = deg_v ⊙ (x @ W)
__device__ float    g_t   [N_E * FT];

// ------------- fused bitmask builder: one pass over H produces both ---------
// block = 256 threads, tile = 32 rows x 256 cols of H
__global__ void __launch_bounds__(256) k_build_bits(const float* __restrict__ H) {
    __shared__ float tile[32][257];
    int e0 = blockIdx.x * 256;
    int n0 = blockIdx.y * 32;
    int t  = threadIdx.x;
    // load tile (coalesced 1KB rows)
#pragma unroll 4
    for (int i = 0; i < 32; i++)
        tile[i][t] = H[(size_t)(n0 + i) * N_E + e0 + t];
    __syncthreads();

    // HTB: ballot down columns (t = w*32 + l over 8 column-groups)
    {
        int w = t >> 5, l = t & 31;
#pragma unroll 4
        for (int j = 0; j < 32; j++) {
            int c = w * 32 + j;
            uint32_t m = __ballot_sync(0xffffffffu, tile[l][c] != 0.f);
            if (l == 0) g_HTB[(size_t)(e0 + c) * WN + blockIdx.y] = m;
        }
    }

    // HB: each thread builds one 32-bit word along a row.
    // r = row in tile (0..31), wi = 32-col word (0..7). Rotated start (wi*4)
    // makes the smem reads conflict-free: bank = (r + wi*4 + kk) mod 32.
    {
        int r = t >> 3, wi = t & 7;
        uint32_t bits = 0;
#pragma unroll
        for (int kk = 0; kk < 32; kk++) {
            int k = (wi * 4 + kk) & 31;
            if (tile[r][wi * 32 + k] != 0.f) bits |= 1u << k;
        }
        g_HB[(size_t)(n0 + r) * WE + blockIdx.x * 8 + wi] = bits;
    }
}

// ---------------- y = x @ V  (one warp per vertex row) ----------------------
__global__ void __launch_bounds__(256) k_xv(const float* __restrict__ x,
                                            const float* __restrict__ V) {
    int n = blockIdx.x * 8 + (threadIdx.x >> 5);
    int l = threadIdx.x & 31;
    float s = 0.f;
#pragma unroll
    for (int i = 0; i < 16; i++) {
        int f = i * 32 + l;
        s += x[(size_t)n * FT + f] * V[f];
    }
#pragma unroll
    for (int o = 16; o; o >>= 1) s += __shfl_xor_sync(0xffffffffu, s, o);
    if (l == 0) g_y[n] = s;
}

// -------- hw = sigmoid(H^T (xV)), deg_e = popcount; write w output ----------
__global__ void __launch_bounds__(128) k_hw_dege(float* __restrict__ w_out) {
    int e = blockIdx.x * 4 + (threadIdx.x >> 5);
    int l = threadIdx.x & 31;
    float s = 0.f;
    int cnt = 0;
#pragma unroll
    for (int i = 0; i < 8; i++) {
        uint32_t w = g_HTB[(size_t)e * WN + l * 8 + i];
        cnt += __popc(w);
        int base = (l * 8 + i) * 32;
        while (w) {
            int k = __ffs(w) - 1; w &= w - 1;
            s += g_y[base + k];
        }
    }
#pragma unroll
    for (int o = 16; o; o >>= 1) {
        s   += __shfl_xor_sync(0xffffffffu, s, o);
        cnt += __shfl_xor_sync(0xffffffffu, cnt, o);
    }
    if (l == 0) {
        float hw = 1.f / (1.f + expf(-s));
        g_hw[e]   = hw;
        w_out[e]  = hw;
        g_dege[e] = (float)cnt;
    }
}

// ---------------- deg_v = H @ hw --------------------------------------------
__global__ void __launch_bounds__(128) k_degv() {
    int n = blockIdx.x * 4 + (threadIdx.x >> 5);
    int l = threadIdx.x & 31;
    float s = 0.f;
#pragma unroll
    for (int jj = 0; jj < 4; jj++) {
        int j = l * 4 + jj;
        uint32_t w = g_HB[(size_t)n * WE + j];
        while (w) { int k = __ffs(w) - 1; w &= w - 1; s += g_hw[j * 32 + k]; }
    }
#pragma unroll
    for (int o = 16; o; o >>= 1) s += __shfl_xor_sync(0xffffffffu, s, o);
    if (l == 0) g_degv[n] = s;
}

// -------- z = deg_v ⊙ (x @ weight)  (fp32 SGEMM 128x128x16, scaled epilogue) -
__global__ void __launch_bounds__(256) k_gemm_xw(const float* __restrict__ A,
                                                 const float* __restrict__ B) {
    __shared__ float As[16][132];
    __shared__ float Bs[16][132];
    int bm = blockIdx.y * 128;
    int bn = blockIdx.x * 128;
    int tid = threadIdx.x;
    int tx = tid & 15, ty = tid >> 4;
    float acc[8][8];
#pragma unroll
    for (int i = 0; i < 8; i++)
#pragma unroll
        for (int j = 0; j < 8; j++) acc[i][j] = 0.f;

    for (int k0 = 0; k0 < FT; k0 += 16) {
#pragma unroll
        for (int r = 0; r < 2; r++) {
            int id = tid + r * 256;
            int ar = id >> 2, ac = (id & 3) * 4;
            float4 av = *reinterpret_cast<const float4*>(&A[(size_t)(bm + ar) * FT + k0 + ac]);
            As[ac + 0][ar] = av.x; As[ac + 1][ar] = av.y;
            As[ac + 2][ar] = av.z; As[ac + 3][ar] = av.w;
            int br = id >> 5, bc = (id & 31) * 4;
            *reinterpret_cast<float4*>(&Bs[br][bc]) =
                *reinterpret_cast<const float4*>(&B[(size_t)(k0 + br) * FT + bn + bc]);
        }
        __syncthreads();
#pragma unroll
        for (int kk = 0; kk < 16; kk++) {
            float a[8], b[8];
#pragma unroll
            for (int i = 0; i < 8; i++) a[i] = As[kk][ty + 16 * i];
#pragma unroll
            for (int i = 0; i < 8; i++) b[i] = Bs[kk][tx + 16 * i];
#pragma unroll
            for (int i = 0; i < 8; i++)
#pragma unroll
                for (int j = 0; j < 8; j++)
                    acc[i][j] += a[i] * b[j];
        }
        __syncthreads();
    }
#pragma unroll
    for (int i = 0; i < 8; i++) {
        int row = bm + ty + 16 * i;
        float dv = g_degv[row];
#pragma unroll
        for (int j = 0; j < 8; j++)
            g_z[(size_t)row * FT + bn + tx + 16 * j] = dv * acc[i][j];
    }
}

// ------------ t = (w*deg_e) ⊙ H^T @ z  (index-list gather, MLP>=4) ----------
#define CAP_E 1024
__global__ void __launch_bounds__(128) k_edge_gather_t() {
    int e = blockIdx.x;
    int tid = threadIdx.x;
    __shared__ int idx[CAP_E];
    __shared__ int cnt;
    if (tid == 0) cnt = 0;
    __syncthreads();
    for (int j = tid; j < WN; j += 128) {
        uint32_t w = g_HTB[(size_t)e * WN + j];
        if (w) {
            int pos = atomicAdd(&cnt, __popc(w));
            while (w) {
                int k = __ffs(w) - 1; w &= w - 1;
                if (pos < CAP_E) idx[pos] = j * 32 + k;
                pos++;
            }
        }
    }
    __syncthreads();
    int m = cnt < CAP_E ? cnt : CAP_E;

    float4 acc = {0.f, 0.f, 0.f, 0.f};
    const float4* z4 = reinterpret_cast<const float4*>(g_z);
    int i = 0;
    for (; i + 4 <= m; i += 4) {
        int n0 = idx[i], n1 = idx[i + 1], n2 = idx[i + 2], n3 = idx[i + 3];
        float4 a = z4[(size_t)n0 * 128 + tid];
        float4 b = z4[(size_t)n1 * 128 + tid];
        float4 c = z4[(size_t)n2 * 128 + tid];
        float4 d = z4[(size_t)n3 * 128 + tid];
        acc.x += a.x + b.x + c.x + d.x;
        acc.y += a.y + b.y + c.y + d.y;
        acc.z += a.z + b.z + c.z + d.z;
        acc.w += a.w + b.w + c.w + d.w;
    }
    for (; i < m; i++) {
        float4 a = z4[(size_t)idx[i] * 128 + tid];
        acc.x += a.x; acc.y += a.y; acc.z += a.z; acc.w += a.w;
    }
    float s = g_hw[e] * g_dege[e];
    float4 r = {s * acc.x, s * acc.y, s * acc.z, s * acc.w};
    reinterpret_cast<float4*>(g_t)[(size_t)e * 128 + tid] = r;
}

// ------------ out = deg_v ⊙ (H @ t) + bias  (index-list gather) -------------
#define CAP_V 512
__global__ void __launch_bounds__(128) k_vertex_gather(const float* __restrict__ bias,
                                                       float* __restrict__ out) {
    int n = blockIdx.x;
    int tid = threadIdx.x;
    __shared__ int idx[CAP_V];
    __shared__ int cnt;
    if (tid == 0) cnt = 0;
    __syncthreads();
    if (tid < WE) {
        uint32_t w = g_HB[(size_t)n * WE + tid];
        if (w) {
            int pos = atomicAdd(&cnt, __popc(w));
            while (w) {
                int k = __ffs(w) - 1; w &= w - 1;
                if (pos < CAP_V) idx[pos] = tid * 32 + k;
                pos++;
            }
        }
    }
    __syncthreads();
    int m = cnt < CAP_V ? cnt : CAP_V;

    float4 acc = {0.f, 0.f, 0.f, 0.f};
    const float4* t4 = reinterpret_cast<const float4*>(g_t);
    int i = 0;
    for (; i + 4 <= m; i += 4) {
        int e0 = idx[i], e1 = idx[i + 1], e2 = idx[i + 2], e3 = idx[i + 3];
        float4 a = t4[(size_t)e0 * 128 + tid];
        float4 b = t4[(size_t)e1 * 128 + tid];
        float4 c = t4[(size_t)e2 * 128 + tid];
        float4 d = t4[(size_t)e3 * 128 + tid];
        acc.x += a.x + b.x + c.x + d.x;
        acc.y += a.y + b.y + c.y + d.y;
        acc.z += a.z + b.z + c.z + d.z;
        acc.w += a.w + b.w + c.w + d.w;
    }
    for (; i < m; i++) {
        float4 a = t4[(size_t)idx[i] * 128 + tid];
        acc.x += a.x; acc.y += a.y; acc.z += a.z; acc.w += a.w;
    }
    float dv = g_degv[n];
    float4 b = reinterpret_cast<const float4*>(bias)[tid];
    float4 r = {dv * acc.x + b.x, dv * acc.y + b.y,
                dv * acc.z + b.z, dv * acc.w + b.w};
    reinterpret_cast<float4*>(out)[(size_t)n * 128 + tid] = r;
}

// ---------------- launch ----------------------------------------------------
extern "C" void kernel_launch(void* const* d_in, const int* in_sizes, int n_in,
                              void* d_out, int out_size) {
    const float* x      = (const float*)d_in[0];   // (8192, 512)
    const float* H      = (const float*)d_in[1];   // (8192, 4096)
    const float* weight = (const float*)d_in[2];   // (512, 512)
    const float* V      = (const float*)d_in[3];   // (512, 1)
    const float* bias   = (const float*)d_in[4];   // (512,)
    float* out   = (float*)d_out;                  // (8192, 512)
    float* w_out = (float*)d_out + (size_t)N_V * FT;  // (4096,)

    k_build_bits<<<dim3(N_E / 256, N_V / 32), 256>>>(H);
    k_xv        <<<N_V / 8, 256>>>(x, V);
    k_hw_dege   <<<N_E / 4, 128>>>(w_out);
    k_degv      <<<N_V / 4, 128>>>();
    k_gemm_xw   <<<dim3(FT / 128, N_V / 128), 256>>>(x, weight);
    k_edge_gather_t<<<N_E, 128>>>();
    k_vertex_gather<<<N_V, 128>>>(bias, out);
}

// round 6
// speedup vs baseline: 2.7819x; 1.0822x over previous
#include <cuda_runtime.h>
#include <cuda_bf16.h>
#include <mma.h>
#include <cstdint>

using namespace nvcuda;

#define N_V 8192
#define N_E 4096
#define FT  512
#define WN  256   // words per HTB row  (N_V/32)
#define WE  128   // words per HB  row  (N_E/32)

// ---------------- scratch (static device globals; no allocation) ------------
__device__ uint32_t g_HB [N_V * WE];
__device__ uint32_t g_HTB[N_E * WN];
__device__ float    g_y   [N_V];        // y = x @ V
__device__ float    g_hw  [N_E];
__device__ float    g_dege[N_E];
__device__ float    g_degv[N_V];
__device__ float    g_z   [(size_t)N_V * FT];   // z = deg_v ⊙ (x @ W)
__device__ float    g_t   [N_E * FT];
__device__ __nv_bfloat16 g_Ah[(size_t)N_V * FT];   // split of deg_v ⊙ x
__device__ __nv_bfloat16 g_Al[(size_t)N_V * FT];
__device__ __nv_bfloat16 g_Bh[FT * FT];            // split of weight
__device__ __nv_bfloat16 g_Bl[FT * FT];

// ------------- fused bitmask builder: one pass over H produces both ---------
__global__ void __launch_bounds__(256) k_build_bits(const float* __restrict__ H) {
    __shared__ float tile[32][257];
    int e0 = blockIdx.x * 256;
    int n0 = blockIdx.y * 32;
    int t  = threadIdx.x;
#pragma unroll 4
    for (int i = 0; i < 32; i++)
        tile[i][t] = H[(size_t)(n0 + i) * N_E + e0 + t];
    __syncthreads();
    {
        int w = t >> 5, l = t & 31;
#pragma unroll 4
        for (int j = 0; j < 32; j++) {
            int c = w * 32 + j;
            uint32_t m = __ballot_sync(0xffffffffu, tile[l][c] != 0.f);
            if (l == 0) g_HTB[(size_t)(e0 + c) * WN + blockIdx.y] = m;
        }
    }
    {
        int r = t >> 3, wi = t & 7;
        uint32_t bits = 0;
#pragma unroll
        for (int kk = 0; kk < 32; kk++) {
            int k = (wi * 4 + kk) & 31;
            if (tile[r][wi * 32 + k] != 0.f) bits |= 1u << k;
        }
        g_HB[(size_t)(n0 + r) * WE + blockIdx.x * 8 + wi] = bits;
    }
}

// ---------------- y = x @ V  (one warp per vertex row) ----------------------
__global__ void __launch_bounds__(256) k_xv(const float* __restrict__ x,
                                            const float* __restrict__ V) {
    int n = blockIdx.x * 8 + (threadIdx.x >> 5);
    int l = threadIdx.x & 31;
    float s = 0.f;
#pragma unroll
    for (int i = 0; i < 16; i++) {
        int f = i * 32 + l;
        s += x[(size_t)n * FT + f] * V[f];
    }
#pragma unroll
    for (int o = 16; o; o >>= 1) s += __shfl_xor_sync(0xffffffffu, s, o);
    if (l == 0) g_y[n] = s;
}

// -------- hw = sigmoid(H^T (xV)), deg_e = popcount; write w output ----------
__global__ void __launch_bounds__(128) k_hw_dege(float* __restrict__ w_out) {
    int e = blockIdx.x * 4 + (threadIdx.x >> 5);
    int l = threadIdx.x & 31;
    float s = 0.f;
    int cnt = 0;
#pragma unroll
    for (int i = 0; i < 8; i++) {
        uint32_t w = g_HTB[(size_t)e * WN + l * 8 + i];
        cnt += __popc(w);
        int base = (l * 8 + i) * 32;
        while (w) {
            int k = __ffs(w) - 1; w &= w - 1;
            s += g_y[base + k];
        }
    }
#pragma unroll
    for (int o = 16; o; o >>= 1) {
        s   += __shfl_xor_sync(0xffffffffu, s, o);
        cnt += __shfl_xor_sync(0xffffffffu, cnt, o);
    }
    if (l == 0) {
        float hw = 1.f / (1.f + expf(-s));
        g_hw[e]   = hw;
        w_out[e]  = hw;
        g_dege[e] = (float)cnt;
    }
}

// ---------------- deg_v = H @ hw --------------------------------------------
__global__ void __launch_bounds__(128) k_degv() {
    int n = blockIdx.x * 4 + (threadIdx.x >> 5);
    int l = threadIdx.x & 31;
    float s = 0.f;
#pragma unroll
    for (int jj = 0; jj < 4; jj++) {
        int j = l * 4 + jj;
        uint32_t w = g_HB[(size_t)n * WE + j];
        while (w) { int k = __ffs(w) - 1; w &= w - 1; s += g_hw[j * 32 + k]; }
    }
#pragma unroll
    for (int o = 16; o; o >>= 1) s += __shfl_xor_sync(0xffffffffu, s, o);
    if (l == 0) g_degv[n] = s;
}

// -------- split A = deg_v ⊙ x into bf16 hi/lo -------------------------------
__global__ void __launch_bounds__(256) k_splitA(const float* __restrict__ x) {
    int gid = blockIdx.x * blockDim.x + threadIdx.x;     // one per 8 elems
    int row = gid >> 6;
    int f   = (gid & 63) * 8;
    float dv = g_degv[row];
    const float4* p = reinterpret_cast<const float4*>(x + (size_t)row * FT + f);
    float v[8];
    float4 a = p[0], b = p[1];
    v[0]=a.x; v[1]=a.y; v[2]=a.z; v[3]=a.w;
    v[4]=b.x; v[5]=b.y; v[6]=b.z; v[7]=b.w;
    __nv_bfloat16 h[8], l[8];
#pragma unroll
    for (int i = 0; i < 8; i++) {
        float s = dv * v[i];
        h[i] = __float2bfloat16(s);
        l[i] = __float2bfloat16(s - __bfloat162float(h[i]));
    }
    size_t off = (size_t)row * FT + f;
    *reinterpret_cast<uint4*>(&g_Ah[off]) = *reinterpret_cast<uint4*>(h);
    *reinterpret_cast<uint4*>(&g_Al[off]) = *reinterpret_cast<uint4*>(l);
}

// -------- split B = weight into bf16 hi/lo ----------------------------------
__global__ void __launch_bounds__(256) k_splitB(const float* __restrict__ W) {
    int gid = blockIdx.x * blockDim.x + threadIdx.x;
    int off0 = gid * 8;
    const float4* p = reinterpret_cast<const float4*>(W + off0);
    float v[8];
    float4 a = p[0], b = p[1];
    v[0]=a.x; v[1]=a.y; v[2]=a.z; v[3]=a.w;
    v[4]=b.x; v[5]=b.y; v[6]=b.z; v[7]=b.w;
    __nv_bfloat16 h[8], l[8];
#pragma unroll
    for (int i = 0; i < 8; i++) {
        h[i] = __float2bfloat16(v[i]);
        l[i] = __float2bfloat16(v[i] - __bfloat162float(h[i]));
    }
    *reinterpret_cast<uint4*>(&g_Bh[off0]) = *reinterpret_cast<uint4*>(h);
    *reinterpret_cast<uint4*>(&g_Bl[off0]) = *reinterpret_cast<uint4*>(l);
}

// ------ z = (deg_v ⊙ x) @ W via dual-bf16 wmma: AhBh + AhBl + AlBh ----------
#define BM 128
#define BN 128
#define BK 32
__global__ void __launch_bounds__(256) k_gemm_wmma() {
    __shared__ __nv_bfloat16 As[BM][BK + 8];    // ld 40 elems = 80B (16B multiple)
    __shared__ __nv_bfloat16 Bs[BK][BN + 8];    // ld 136 elems = 272B
    int bm = blockIdx.y * BM;
    int bn = blockIdx.x * BN;
    int tid = threadIdx.x;
    int wid = tid >> 5;
    int wy = wid >> 2;       // 0..1  -> 64 rows each
    int wx = wid & 3;        // 0..3  -> 32 cols each

    wmma::fragment<wmma::accumulator, 16, 16, 16, float> acc[4][2];
#pragma unroll
    for (int i = 0; i < 4; i++)
#pragma unroll
        for (int j = 0; j < 2; j++) wmma::fill_fragment(acc[i][j], 0.f);

#pragma unroll
    for (int p = 0; p < 3; p++) {
        const __nv_bfloat16* gA = (p < 2) ? g_Ah : g_Al;
        const __nv_bfloat16* gB = (p == 1) ? g_Bl : g_Bh;
        for (int k0 = 0; k0 < FT; k0 += BK) {
#pragma unroll
            for (int r = 0; r < 2; r++) {
                int id = tid + r * 256;
                int arow = id >> 2, av = id & 3;
                *reinterpret_cast<uint4*>(&As[arow][av * 8]) =
                    *reinterpret_cast<const uint4*>(&gA[(size_t)(bm + arow) * FT + k0 + av * 8]);
                int brow = id >> 4, bv = id & 15;
                *reinterpret_cast<uint4*>(&Bs[brow][bv * 8]) =
                    *reinterpret_cast<const uint4*>(&gB[(size_t)(k0 + brow) * FT + bn + bv * 8]);
            }
            __syncthreads();
#pragma unroll
            for (int kk = 0; kk < 2; kk++) {
                wmma::fragment<wmma::matrix_a, 16, 16, 16, __nv_bfloat16, wmma::row_major> af[4];
                wmma::fragment<wmma::matrix_b, 16, 16, 16, __nv_bfloat16, wmma::row_major> bf[2];
#pragma unroll
                for (int i = 0; i < 4; i++)
                    wmma::load_matrix_sync(af[i], &As[wy * 64 + i * 16][kk * 16], BK + 8);
#pragma unroll
                for (int j = 0; j < 2; j++)
                    wmma::load_matrix_sync(bf[j], &Bs[kk * 16][wx * 32 + j * 16], BN + 8);
#pragma unroll
                for (int i = 0; i < 4; i++)
#pragma unroll
                    for (int j = 0; j < 2; j++)
                        wmma::mma_sync(acc[i][j], af[i], bf[j], acc[i][j]);
            }
            __syncthreads();
        }
    }
#pragma unroll
    for (int i = 0; i < 4; i++) {
        int row = bm + wy * 64 + i * 16;
#pragma unroll
        for (int j = 0; j < 2; j++) {
            int col = bn + wx * 32 + j * 16;
            wmma::store_matrix_sync(&g_z[(size_t)row * FT + col], acc[i][j],
                                    FT, wmma::mem_row_major);
        }
    }
}

// ------------ t = (w*deg_e) ⊙ H^T @ z  (index-list gather) ------------------
#define CAP_E 1024
__global__ void __launch_bounds__(128) k_edge_gather_t() {
    int e = blockIdx.x;
    int tid = threadIdx.x;
    __shared__ int idx[CAP_E];
    __shared__ int cnt;
    if (tid == 0) cnt = 0;
    __syncthreads();
    for (int j = tid; j < WN; j += 128) {
        uint32_t w = g_HTB[(size_t)e * WN + j];
        if (w) {
            int pos = atomicAdd(&cnt, __popc(w));
            while (w) {
                int k = __ffs(w) - 1; w &= w - 1;
                if (pos < CAP_E) idx[pos] = j * 32 + k;
                pos++;
            }
        }
    }
    __syncthreads();
    int m = cnt < CAP_E ? cnt : CAP_E;

    float4 acc = {0.f, 0.f, 0.f, 0.f};
    const float4* z4 = reinterpret_cast<const float4*>(g_z);
    int i = 0;
    for (; i + 4 <= m; i += 4) {
        int n0 = idx[i], n1 = idx[i + 1], n2 = idx[i + 2], n3 = idx[i + 3];
        float4 a = z4[(size_t)n0 * 128 + tid];
        float4 b = z4[(size_t)n1 * 128 + tid];
        float4 c = z4[(size_t)n2 * 128 + tid];
        float4 d = z4[(size_t)n3 * 128 + tid];
        acc.x += a.x + b.x + c.x + d.x;
        acc.y += a.y + b.y + c.y + d.y;
        acc.z += a.z + b.z + c.z + d.z;
        acc.w += a.w + b.w + c.w + d.w;
    }
    for (; i < m; i++) {
        float4 a = z4[(size_t)idx[i] * 128 + tid];
        acc.x += a.x; acc.y += a.y; acc.z += a.z; acc.w += a.w;
    }
    float s = g_hw[e] * g_dege[e];
    float4 r = {s * acc.x, s * acc.y, s * acc.z, s * acc.w};
    reinterpret_cast<float4*>(g_t)[(size_t)e * 128 + tid] = r;
}

// ------------ out = deg_v ⊙ (H @ t) + bias  (index-list gather) -------------
#define CAP_V 512
__global__ void __launch_bounds__(128) k_vertex_gather(const float* __restrict__ bias,
                                                       float* __restrict__ out) {
    int n = blockIdx.x;
    int tid = threadIdx.x;
    __shared__ int idx[CAP_V];
    __shared__ int cnt;
    if (tid == 0) cnt = 0;
    __syncthreads();
    if (tid < WE) {
        uint32_t w = g_HB[(size_t)n * WE + tid];
        if (w) {
            int pos = atomicAdd(&cnt, __popc(w));
            while (w) {
                int k = __ffs(w) - 1; w &= w - 1;
                if (pos < CAP_V) idx[pos] = tid * 32 + k;
                pos++;
            }
        }
    }
    __syncthreads();
    int m = cnt < CAP_V ? cnt : CAP_V;

    float4 acc = {0.f, 0.f, 0.f, 0.f};
    const float4* t4 = reinterpret_cast<const float4*>(g_t);
    int i = 0;
    for (; i + 4 <= m; i += 4) {
        int e0 = idx[i], e1 = idx[i + 1], e2 = idx[i + 2], e3 = idx[i + 3];
        float4 a = t4[(size_t)e0 * 128 + tid];
        float4 b = t4[(size_t)e1 * 128 + tid];
        float4 c = t4[(size_t)e2 * 128 + tid];
        float4 d = t4[(size_t)e3 * 128 + tid];
        acc.x += a.x + b.x + c.x + d.x;
        acc.y += a.y + b.y + c.y + d.y;
        acc.z += a.z + b.z + c.z + d.z;
        acc.w += a.w + b.w + c.w + d.w;
    }
    for (; i < m; i++) {
        float4 a = t4[(size_t)idx[i] * 128 + tid];
        acc.x += a.x; acc.y += a.y; acc.z += a.z; acc.w += a.w;
    }
    float dv = g_degv[n];
    float4 b = reinterpret_cast<const float4*>(bias)[tid];
    float4 r = {dv * acc.x + b.x, dv * acc.y + b.y,
                dv * acc.z + b.z, dv * acc.w + b.w};
    reinterpret_cast<float4*>(out)[(size_t)n * 128 + tid] = r;
}

// ---------------- launch ----------------------------------------------------
extern "C" void kernel_launch(void* const* d_in, const int* in_sizes, int n_in,
                              void* d_out, int out_size) {
    const float* x      = (const float*)d_in[0];   // (8192, 512)
    const float* H      = (const float*)d_in[1];   // (8192, 4096)
    const float* weight = (const float*)d_in[2];   // (512, 512)
    const float* V      = (const float*)d_in[3];   // (512, 1)
    const float* bias   = (const float*)d_in[4];   // (512,)
    float* out   = (float*)d_out;                  // (8192, 512)
    float* w_out = (float*)d_out + (size_t)N_V * FT;  // (4096,)

    k_build_bits<<<dim3(N_E / 256, N_V / 32), 256>>>(H);
    k_xv        <<<N_V / 8, 256>>>(x, V);
    k_splitB    <<<(FT * FT / 8) / 256, 256>>>(weight);
    k_hw_dege   <<<N_E / 4, 128>>>(w_out);
    k_degv      <<<N_V / 4, 128>>>();
    k_splitA    <<<(N_V * 64) / 256, 256>>>(x);
    k_gemm_wmma <<<dim3(FT / BN, N_V / BM), 256>>>();
    k_edge_gather_t<<<N_E, 128>>>();
    k_vertex_gather<<<N_V, 128>>>(bias, out);
}

// round 7
// speedup vs baseline: 3.1711x; 1.1399x over previous
#include <cuda_runtime.h>
#include <cuda_bf16.h>
#include <cuda_fp16.h>
#include <mma.h>
#include <cstdint>

using namespace nvcuda;

#define N_V 8192
#define N_E 4096
#define FT  512
#define WN  256   // words per HTB row  (N_V/32)
#define WE  128   // words per HB  row  (N_E/32)

// ---------------- scratch (static device globals; no allocation) ------------
__device__ uint32_t g_HB [N_V * WE];
__device__ uint32_t g_HTB[N_E * WN];
__device__ float    g_y   [N_V];
__device__ float    g_hw  [N_E];
__device__ float    g_dege[N_E];
__device__ float    g_degv[N_V];
__device__ float    g_z   [(size_t)N_V * FT];    // fp32 GEMM out (staging)
__device__ __half   g_zh  [(size_t)N_V * FT];    // fp16 z for gather
__device__ __half   g_th  [N_E * FT];            // fp16 t (scaled by 2^-8)
__device__ __nv_bfloat16 g_Ah[(size_t)N_V * FT];
__device__ __nv_bfloat16 g_Al[(size_t)N_V * FT];
__device__ __nv_bfloat16 g_Bh[FT * FT];
__device__ __nv_bfloat16 g_Bl[FT * FT];

// ------------- fused bitmask builder ----------------------------------------
__global__ void __launch_bounds__(256) k_build_bits(const float* __restrict__ H) {
    __shared__ float tile[32][257];
    int e0 = blockIdx.x * 256;
    int n0 = blockIdx.y * 32;
    int t  = threadIdx.x;
#pragma unroll 4
    for (int i = 0; i < 32; i++)
        tile[i][t] = H[(size_t)(n0 + i) * N_E + e0 + t];
    __syncthreads();
    {
        int w = t >> 5, l = t & 31;
#pragma unroll 4
        for (int j = 0; j < 32; j++) {
            int c = w * 32 + j;
            uint32_t m = __ballot_sync(0xffffffffu, tile[l][c] != 0.f);
            if (l == 0) g_HTB[(size_t)(e0 + c) * WN + blockIdx.y] = m;
        }
    }
    {
        int r = t >> 3, wi = t & 7;
        uint32_t bits = 0;
#pragma unroll
        for (int kk = 0; kk < 32; kk++) {
            int k = (wi * 4 + kk) & 31;
            if (tile[r][wi * 32 + k] != 0.f) bits |= 1u << k;
        }
        g_HB[(size_t)(n0 + r) * WE + blockIdx.x * 8 + wi] = bits;
    }
}

// ---------------- y = x @ V --------------------------------------------------
__global__ void __launch_bounds__(256) k_xv(const float* __restrict__ x,
                                            const float* __restrict__ V) {
    int n = blockIdx.x * 8 + (threadIdx.x >> 5);
    int l = threadIdx.x & 31;
    float s = 0.f;
#pragma unroll
    for (int i = 0; i < 16; i++) {
        int f = i * 32 + l;
        s += x[(size_t)n * FT + f] * V[f];
    }
#pragma unroll
    for (int o = 16; o; o >>= 1) s += __shfl_xor_sync(0xffffffffu, s, o);
    if (l == 0) g_y[n] = s;
}

// -------- hw = sigmoid(H^T (xV)), deg_e; write w output ----------------------
__global__ void __launch_bounds__(128) k_hw_dege(float* __restrict__ w_out) {
    int e = blockIdx.x * 4 + (threadIdx.x >> 5);
    int l = threadIdx.x & 31;
    float s = 0.f;
    int cnt = 0;
#pragma unroll
    for (int i = 0; i < 8; i++) {
        uint32_t w = g_HTB[(size_t)e * WN + l * 8 + i];
        cnt += __popc(w);
        int base = (l * 8 + i) * 32;
        while (w) {
            int k = __ffs(w) - 1; w &= w - 1;
            s += g_y[base + k];
        }
    }
#pragma unroll
    for (int o = 16; o; o >>= 1) {
        s   += __shfl_xor_sync(0xffffffffu, s, o);
        cnt += __shfl_xor_sync(0xffffffffu, cnt, o);
    }
    if (l == 0) {
        float hw = 1.f / (1.f + expf(-s));
        g_hw[e]   = hw;
        w_out[e]  = hw;
        g_dege[e] = (float)cnt;
    }
}

// ---------------- deg_v = H @ hw ---------------------------------------------
__global__ void __launch_bounds__(128) k_degv() {
    int n = blockIdx.x * 4 + (threadIdx.x >> 5);
    int l = threadIdx.x & 31;
    float s = 0.f;
#pragma unroll
    for (int jj = 0; jj < 4; jj++) {
        int j = l * 4 + jj;
        uint32_t w = g_HB[(size_t)n * WE + j];
        while (w) { int k = __ffs(w) - 1; w &= w - 1; s += g_hw[j * 32 + k]; }
    }
#pragma unroll
    for (int o = 16; o; o >>= 1) s += __shfl_xor_sync(0xffffffffu, s, o);
    if (l == 0) g_degv[n] = s;
}

// -------- split A = deg_v ⊙ x into bf16 hi/lo --------------------------------
__global__ void __launch_bounds__(256) k_splitA(const float* __restrict__ x) {
    int gid = blockIdx.x * blockDim.x + threadIdx.x;
    int row = gid >> 6;
    int f   = (gid & 63) * 8;
    float dv = g_degv[row];
    const float4* p = reinterpret_cast<const float4*>(x + (size_t)row * FT + f);
    float v[8];
    float4 a = p[0], b = p[1];
    v[0]=a.x; v[1]=a.y; v[2]=a.z; v[3]=a.w;
    v[4]=b.x; v[5]=b.y; v[6]=b.z; v[7]=b.w;
    __nv_bfloat16 h[8], l[8];
#pragma unroll
    for (int i = 0; i < 8; i++) {
        float s = dv * v[i];
        h[i] = __float2bfloat16(s);
        l[i] = __float2bfloat16(s - __bfloat162float(h[i]));
    }
    size_t off = (size_t)row * FT + f;
    *reinterpret_cast<uint4*>(&g_Ah[off]) = *reinterpret_cast<uint4*>(h);
    *reinterpret_cast<uint4*>(&g_Al[off]) = *reinterpret_cast<uint4*>(l);
}

// -------- split B = weight into bf16 hi/lo -----------------------------------
__global__ void __launch_bounds__(256) k_splitB(const float* __restrict__ W) {
    int gid = blockIdx.x * blockDim.x + threadIdx.x;
    int off0 = gid * 8;
    const float4* p = reinterpret_cast<const float4*>(W + off0);
    float v[8];
    float4 a = p[0], b = p[1];
    v[0]=a.x; v[1]=a.y; v[2]=a.z; v[3]=a.w;
    v[4]=b.x; v[5]=b.y; v[6]=b.z; v[7]=b.w;
    __nv_bfloat16 h[8], l[8];
#pragma unroll
    for (int i = 0; i < 8; i++) {
        h[i] = __float2bfloat16(v[i]);
        l[i] = __float2bfloat16(v[i] - __bfloat162float(h[i]));
    }
    *reinterpret_cast<uint4*>(&g_Bh[off0]) = *reinterpret_cast<uint4*>(h);
    *reinterpret_cast<uint4*>(&g_Bl[off0]) = *reinterpret_cast<uint4*>(l);
}

// ------ z = (deg_v ⊙ x) @ W via dual-bf16 wmma -------------------------------
#define BM 128
#define BN 128
#define BK 32
__global__ void __launch_bounds__(256) k_gemm_wmma() {
    __shared__ __nv_bfloat16 As[BM][BK + 8];
    __shared__ __nv_bfloat16 Bs[BK][BN + 8];
    int bm = blockIdx.y * BM;
    int bn = blockIdx.x * BN;
    int tid = threadIdx.x;
    int wid = tid >> 5;
    int wy = wid >> 2;
    int wx = wid & 3;

    wmma::fragment<wmma::accumulator, 16, 16, 16, float> acc[4][2];
#pragma unroll
    for (int i = 0; i < 4; i++)
#pragma unroll
        for (int j = 0; j < 2; j++) wmma::fill_fragment(acc[i][j], 0.f);

#pragma unroll
    for (int p = 0; p < 3; p++) {
        const __nv_bfloat16* gA = (p < 2) ? g_Ah : g_Al;
        const __nv_bfloat16* gB = (p == 1) ? g_Bl : g_Bh;
        for (int k0 = 0; k0 < FT; k0 += BK) {
#pragma unroll
            for (int r = 0; r < 2; r++) {
                int id = tid + r * 256;
                int arow = id >> 2, av = id & 3;
                *reinterpret_cast<uint4*>(&As[arow][av * 8]) =
                    *reinterpret_cast<const uint4*>(&gA[(size_t)(bm + arow) * FT + k0 + av * 8]);
                int brow = id >> 4, bv = id & 15;
                *reinterpret_cast<uint4*>(&Bs[brow][bv * 8]) =
                    *reinterpret_cast<const uint4*>(&gB[(size_t)(k0 + brow) * FT + bn + bv * 8]);
            }
            __syncthreads();
#pragma unroll
            for (int kk = 0; kk < 2; kk++) {
                wmma::fragment<wmma::matrix_a, 16, 16, 16, __nv_bfloat16, wmma::row_major> af[4];
                wmma::fragment<wmma::matrix_b, 16, 16, 16, __nv_bfloat16, wmma::row_major> bf[2];
#pragma unroll
                for (int i = 0; i < 4; i++)
                    wmma::load_matrix_sync(af[i], &As[wy * 64 + i * 16][kk * 16], BK + 8);
#pragma unroll
                for (int j = 0; j < 2; j++)
                    wmma::load_matrix_sync(bf[j], &Bs[kk * 16][wx * 32 + j * 16], BN + 8);
#pragma unroll
                for (int i = 0; i < 4; i++)
#pragma unroll
                    for (int j = 0; j < 2; j++)
                        wmma::mma_sync(acc[i][j], af[i], bf[j], acc[i][j]);
            }
            __syncthreads();
        }
    }
#pragma unroll
    for (int i = 0; i < 4; i++) {
        int row = bm + wy * 64 + i * 16;
#pragma unroll
        for (int j = 0; j < 2; j++) {
            int col = bn + wx * 32 + j * 16;
            wmma::store_matrix_sync(&g_z[(size_t)row * FT + col], acc[i][j],
                                    FT, wmma::mem_row_major);
        }
    }
}

// -------- convert z fp32 -> fp16 ---------------------------------------------
__global__ void __launch_bounds__(256) k_convert_z() {
    int gid = blockIdx.x * blockDim.x + threadIdx.x;   // one per 8 elems
    size_t off = (size_t)gid * 8;
    float4 a = *reinterpret_cast<const float4*>(&g_z[off]);
    float4 b = *reinterpret_cast<const float4*>(&g_z[off + 4]);
    __half2 h[4];
    h[0] = __floats2half2_rn(a.x, a.y);
    h[1] = __floats2half2_rn(a.z, a.w);
    h[2] = __floats2half2_rn(b.x, b.y);
    h[3] = __floats2half2_rn(b.z, b.w);
    *reinterpret_cast<uint4*>(&g_zh[off]) = *reinterpret_cast<uint4*>(h);
}

__device__ __forceinline__ void add_h4(float4& acc, uint2 v) {
    float2 p = __half22float2(*reinterpret_cast<__half2*>(&v.x));
    float2 q = __half22float2(*reinterpret_cast<__half2*>(&v.y));
    acc.x += p.x; acc.y += p.y; acc.z += q.x; acc.w += q.y;
}

// ------------ t = (w*deg_e/256) ⊙ H^T @ z  (fp16 gather) --------------------
#define CAP_E 1024
__global__ void __launch_bounds__(128) k_edge_gather_t() {
    int e = blockIdx.x;
    int tid = threadIdx.x;
    __shared__ int idx[CAP_E];
    __shared__ int cnt;
    if (tid == 0) cnt = 0;
    __syncthreads();
    for (int j = tid; j < WN; j += 128) {
        uint32_t w = g_HTB[(size_t)e * WN + j];
        if (w) {
            int pos = atomicAdd(&cnt, __popc(w));
            while (w) {
                int k = __ffs(w) - 1; w &= w - 1;
                if (pos < CAP_E) idx[pos] = j * 32 + k;
                pos++;
            }
        }
    }
    __syncthreads();
    int m = cnt < CAP_E ? cnt : CAP_E;

    float4 acc = {0.f, 0.f, 0.f, 0.f};
    const uint2* z2 = reinterpret_cast<const uint2*>(g_zh);
    int i = 0;
    for (; i + 4 <= m; i += 4) {
        uint2 a = z2[(size_t)idx[i]     * 128 + tid];
        uint2 b = z2[(size_t)idx[i + 1] * 128 + tid];
        uint2 c = z2[(size_t)idx[i + 2] * 128 + tid];
        uint2 d = z2[(size_t)idx[i + 3] * 128 + tid];
        add_h4(acc, a); add_h4(acc, b); add_h4(acc, c); add_h4(acc, d);
    }
    for (; i < m; i++) add_h4(acc, z2[(size_t)idx[i] * 128 + tid]);

    float s = g_hw[e] * g_dege[e] * (1.f / 256.f);   // 2^-8 scale for fp16 range
    __half2 r[2];
    r[0] = __floats2half2_rn(s * acc.x, s * acc.y);
    r[1] = __floats2half2_rn(s * acc.z, s * acc.w);
    reinterpret_cast<uint2*>(g_th)[(size_t)e * 128 + tid] = *reinterpret_cast<uint2*>(r);
}

// ------------ out = deg_v*256 ⊙ (H @ t) + bias  (fp16 gather) ---------------
#define CAP_V 512
__global__ void __launch_bounds__(128) k_vertex_gather(const float* __restrict__ bias,
                                                       float* __restrict__ out) {
    int n = blockIdx.x;
    int tid = threadIdx.x;
    __shared__ int idx[CAP_V];
    __shared__ int cnt;
    if (tid == 0) cnt = 0;
    __syncthreads();
    if (tid < WE) {
        uint32_t w = g_HB[(size_t)n * WE + tid];
        if (w) {
            int pos = atomicAdd(&cnt, __popc(w));
            while (w) {
                int k = __ffs(w) - 1; w &= w - 1;
                if (pos < CAP_V) idx[pos] = tid * 32 + k;
                pos++;
            }
        }
    }
    __syncthreads();
    int m = cnt < CAP_V ? cnt : CAP_V;

    float4 acc = {0.f, 0.f, 0.f, 0.f};
    const uint2* t2 = reinterpret_cast<const uint2*>(g_th);
    int i = 0;
    for (; i + 4 <= m; i += 4) {
        uint2 a = t2[(size_t)idx[i]     * 128 + tid];
        uint2 b = t2[(size_t)idx[i + 1] * 128 + tid];
        uint2 c = t2[(size_t)idx[i + 2] * 128 + tid];
        uint2 d = t2[(size_t)idx[i + 3] * 128 + tid];
        add_h4(acc, a); add_h4(acc, b); add_h4(acc, c); add_h4(acc, d);
    }
    for (; i < m; i++) add_h4(acc, t2[(size_t)idx[i] * 128 + tid]);

    float dv = g_degv[n] * 256.f;                    // undo 2^-8 scale
    float4 b = reinterpret_cast<const float4*>(bias)[tid];
    float4 r = {dv * acc.x + b.x, dv * acc.y + b.y,
                dv * acc.z + b.z, dv * acc.w + b.w};
    reinterpret_cast<float4*>(out)[(size_t)n * 128 + tid] = r;
}

// ---------------- launch -----------------------------------------------------
extern "C" void kernel_launch(void* const* d_in, const int* in_sizes, int n_in,
                              void* d_out, int out_size) {
    const float* x      = (const float*)d_in[0];
    const float* H      = (const float*)d_in[1];
    const float* weight = (const float*)d_in[2];
    const float* V      = (const float*)d_in[3];
    const float* bias   = (const float*)d_in[4];
    float* out   = (float*)d_out;
    float* w_out = (float*)d_out + (size_t)N_V * FT;

    k_build_bits<<<dim3(N_E / 256, N_V / 32), 256>>>(H);
    k_xv        <<<N_V / 8, 256>>>(x, V);
    k_splitB    <<<(FT * FT / 8) / 256, 256>>>(weight);
    k_hw_dege   <<<N_E / 4, 128>>>(w_out);
    k_degv      <<<N_V / 4, 128>>>();
    k_splitA    <<<(N_V * 64) / 256, 256>>>(x);
    k_gemm_wmma <<<dim3(FT / BN, N_V / BM), 256>>>();
    k_convert_z <<<((size_t)N_V * FT / 8) / 256, 256>>>();
    k_edge_gather_t<<<N_E, 128>>>();
    k_vertex_gather<<<N_V, 128>>>(bias, out);
}